// round 1
// baseline (speedup 1.0000x reference)
#include <cuda_runtime.h>
#include <cstdint>

#define NN 100000

// ---------------- scratch (static device globals; no allocations) ----------
__device__ __align__(256) float g_degout[NN];
__device__ __align__(256) float g_degin[NN];
__device__ __align__(256) float g_snorm[NN];
__device__ __align__(256) float g_dnorm[NN];
__device__ __align__(256) float g_agg[(size_t)NN * 256];   // 102.4 MB
__device__ __align__(256) float g_h[(size_t)NN * 256];     // 102.4 MB
__device__ __align__(256) float g_xm[(size_t)NN * 64];     // 25.6 MB
__device__ __align__(256) float g_agg64[(size_t)NN * 64];  // 25.6 MB

// ---------------- helpers ---------------------------------------------------
__device__ __forceinline__ void red4(float* p, float4 v) {
    asm volatile("red.global.add.v4.f32 [%0], {%1,%2,%3,%4};"
                 :: "l"(p), "f"(v.x), "f"(v.y), "f"(v.z), "f"(v.w)
                 : "memory");
}

// ---------------- zero / degree / norm --------------------------------------
__global__ void zero_deg_kernel() {
    int i = blockIdx.x * blockDim.x + threadIdx.x;
    if (i < NN) { g_degout[i] = 0.f; g_degin[i] = 0.f; }
}

__global__ void degree_kernel(const int* __restrict__ src,
                              const int* __restrict__ dst, int nE) {
    int i = blockIdx.x * blockDim.x + threadIdx.x;
    if (i < nE) {
        atomicAdd(&g_degout[src[i]], 1.f);
        atomicAdd(&g_degin[dst[i]], 1.f);
    }
}

__global__ void norm_kernel() {
    int i = blockIdx.x * blockDim.x + threadIdx.x;
    if (i < NN) {
        g_snorm[i] = rsqrtf(fmaxf(g_degout[i], 1.f));
        g_dnorm[i] = rsqrtf(fmaxf(g_degin[i], 1.f));
    }
}

__global__ void zero_agg256_kernel() {
    int i = blockIdx.x * blockDim.x + threadIdx.x;
    if (i < NN * 64) ((float4*)g_agg)[i] = make_float4(0.f, 0.f, 0.f, 0.f);
}

__global__ void zero_agg64_kernel() {
    int i = blockIdx.x * blockDim.x + threadIdx.x;
    if (i < NN * 16) ((float4*)g_agg64)[i] = make_float4(0.f, 0.f, 0.f, 0.f);
}

// ---------------- scatter (segment_sum over edges) --------------------------
// one edge per warp, F=256: lane covers [4*lane,4*lane+3] and [128+4*lane, ...]
// agg[dst] += x[src] * snorm[src]
__global__ void scatter256_kernel(const float* __restrict__ x,
                                  const int* __restrict__ src,
                                  const int* __restrict__ dst, int nE) {
    int gt = blockIdx.x * blockDim.x + threadIdx.x;
    int e = gt >> 5;
    int lane = gt & 31;
    if (e >= nE) return;
    int s = __ldg(&src[e]);
    int d = __ldg(&dst[e]);
    float w = __ldg(&g_snorm[s]);
    const float4* xr = (const float4*)(x + (size_t)s * 256);
    float4 a = __ldg(&xr[lane]);
    float4 b = __ldg(&xr[lane + 32]);
    a.x *= w; a.y *= w; a.z *= w; a.w *= w;
    b.x *= w; b.y *= w; b.z *= w; b.w *= w;
    float* op = g_agg + (size_t)d * 256;
    red4(op + lane * 4, a);
    red4(op + 128 + lane * 4, b);
}

// one edge per 16 lanes, F=64 (no norm — already folded into the GEMM)
__global__ void scatter64_kernel(const float* __restrict__ x,
                                 const int* __restrict__ src,
                                 const int* __restrict__ dst, int nE) {
    int gt = blockIdx.x * blockDim.x + threadIdx.x;
    int e = gt >> 4;
    int l16 = gt & 15;
    if (e >= nE) return;
    int s = __ldg(&src[e]);
    int d = __ldg(&dst[e]);
    const float4* xr = (const float4*)(x + (size_t)s * 64);
    float4 a = __ldg(&xr[l16]);
    red4(g_agg64 + (size_t)d * 64 + l16 * 4, a);
}

// ---------------- SGEMM: C = act( (A * norm[:,None]) @ W ) -------------------
// K = 256 fixed. BM=128, BK=8, 256 threads, thread tile TM=8 x TN.
template <int BN, int TN, bool RELU>
__global__ __launch_bounds__(256, 2) void gemm_kernel(
    const float* __restrict__ A, const float* __restrict__ W,
    const float* __restrict__ norm, float* __restrict__ C, int M, int N) {
    constexpr int BM = 128, BK = 8, TM = 8;
    __shared__ float As[BK][BM];
    __shared__ float Ws[BK][BN];

    const int t = threadIdx.x;
    const int tr = t >> 4;   // 0..15
    const int tc = t & 15;   // 0..15
    const int row0 = blockIdx.x * BM;
    const int col0 = blockIdx.y * BN;

    // A tile load mapping: 128x8 = 1024 floats = 256 float4 (1 per thread)
    const int a_row = t >> 1;
    const int a_k4 = (t & 1) << 2;
    const bool a_ok = (row0 + a_row) < M;
    const float nrm = a_ok ? __ldg(&norm[row0 + a_row]) : 0.f;
    const float* Aptr = A + (size_t)(row0 + a_row) * 256 + a_k4;

    float acc[TM][TN];
#pragma unroll
    for (int i = 0; i < TM; i++)
#pragma unroll
        for (int j = 0; j < TN; j++) acc[i][j] = 0.f;

    for (int k0 = 0; k0 < 256; k0 += BK) {
        float4 av = make_float4(0.f, 0.f, 0.f, 0.f);
        if (a_ok) av = *(const float4*)(Aptr + k0);
        As[a_k4 + 0][a_row] = av.x * nrm;
        As[a_k4 + 1][a_row] = av.y * nrm;
        As[a_k4 + 2][a_row] = av.z * nrm;
        As[a_k4 + 3][a_row] = av.w * nrm;

        if (BN == 128) {
            int wk = t >> 5;            // 0..7
            int wc = (t & 31) << 2;     // 0..124
            float4 wv = *(const float4*)&W[(size_t)(k0 + wk) * N + col0 + wc];
            *(float4*)&Ws[wk][wc] = wv;
        } else {  // BN == 64: 512 floats = 128 float4
            if (t < (BK * BN / 4)) {
                int wk = t / (BN / 4);
                int wc = (t % (BN / 4)) * 4;
                float4 wv = *(const float4*)&W[(size_t)(k0 + wk) * N + col0 + wc];
                *(float4*)&Ws[wk][wc] = wv;
            }
        }
        __syncthreads();

#pragma unroll
        for (int k = 0; k < BK; k++) {
            float a[TM], b[TN];
            *(float4*)&a[0] = *(float4*)&As[k][tr * TM];
            *(float4*)&a[4] = *(float4*)&As[k][tr * TM + 4];
            *(float4*)&b[0] = *(float4*)&Ws[k][tc * TN];
            if (TN == 8) *(float4*)&b[4] = *(float4*)&Ws[k][tc * TN + 4];
#pragma unroll
            for (int i = 0; i < TM; i++)
#pragma unroll
                for (int j = 0; j < TN; j++) acc[i][j] += a[i] * b[j];
        }
        __syncthreads();
    }

#pragma unroll
    for (int i = 0; i < TM; i++) {
        int r = row0 + tr * TM + i;
        if (r < M) {
            float* crow = C + (size_t)r * N + col0 + tc * TN;
#pragma unroll
            for (int j = 0; j < TN; j += 4) {
                float4 v = make_float4(acc[i][j], acc[i][j + 1],
                                       acc[i][j + 2], acc[i][j + 3]);
                if (RELU) {
                    v.x = fmaxf(v.x, 0.f); v.y = fmaxf(v.y, 0.f);
                    v.z = fmaxf(v.z, 0.f); v.w = fmaxf(v.w, 0.f);
                }
                *(float4*)(crow + j) = v;
            }
        }
    }
}

// ---------------- final: out = agg64 * dst_norm ------------------------------
__global__ void final_kernel(float* __restrict__ out) {
    int i = blockIdx.x * blockDim.x + threadIdx.x;
    if (i >= NN * 16) return;
    float w = g_dnorm[i >> 4];
    float4 v = ((const float4*)g_agg64)[i];
    v.x *= w; v.y *= w; v.z *= w; v.w *= w;
    ((float4*)out)[i] = v;
}

// ---------------- launch -----------------------------------------------------
extern "C" void kernel_launch(void* const* d_in, const int* in_sizes, int n_in,
                              void* d_out, int out_size) {
    const float* feat = (const float*)d_in[0];
    const int* src = (const int*)d_in[1];
    const int* dst = (const int*)d_in[2];
    const float* W0 = (const float*)d_in[3];
    const float* W1 = (const float*)d_in[4];
    const float* W2 = (const float*)d_in[5];
    float* out = (float*)d_out;
    const int nE = in_sizes[1];

    float *agg, *h, *xm, *snorm, *dnorm;
    cudaGetSymbolAddress((void**)&agg, g_agg);
    cudaGetSymbolAddress((void**)&h, g_h);
    cudaGetSymbolAddress((void**)&xm, g_xm);
    cudaGetSymbolAddress((void**)&snorm, g_snorm);
    cudaGetSymbolAddress((void**)&dnorm, g_dnorm);

    const int T = 256;
    const int gemm_rows = (NN + 127) / 128;  // 782

    // degrees + norms
    zero_deg_kernel<<<(NN + T - 1) / T, T>>>();
    degree_kernel<<<(nE + T - 1) / T, T>>>(src, dst, nE);
    norm_kernel<<<(NN + T - 1) / T, T>>>();

    // ---- layer 0: agg = A^T (feat * snorm); h = relu((agg*dnorm) @ W0) ----
    zero_agg256_kernel<<<(NN * 64 + T - 1) / T, T>>>();
    {
        long long thr = (long long)nE * 32;
        scatter256_kernel<<<(int)((thr + T - 1) / T), T>>>(feat, src, dst, nE);
    }
    gemm_kernel<128, 8, true><<<dim3(gemm_rows, 2), T>>>(agg, W0, dnorm, h, NN, 256);

    // ---- layer 1 ----
    zero_agg256_kernel<<<(NN * 64 + T - 1) / T, T>>>();
    {
        long long thr = (long long)nE * 32;
        scatter256_kernel<<<(int)((thr + T - 1) / T), T>>>(h, src, dst, nE);
    }
    gemm_kernel<128, 8, true><<<dim3(gemm_rows, 2), T>>>(agg, W1, dnorm, h, NN, 256);

    // ---- layer 2: xm = (h * snorm) @ W2; out = (A^T xm) * dnorm ----
    gemm_kernel<64, 4, false><<<dim3(gemm_rows, 1), T>>>(h, W2, snorm, xm, NN, 64);
    zero_agg64_kernel<<<(NN * 16 + T - 1) / T, T>>>();
    {
        long long thr = (long long)nE * 16;
        scatter64_kernel<<<(int)((thr + T - 1) / T), T>>>(xm, src, dst, nE);
    }
    final_kernel<<<(NN * 16 + T - 1) / T, T>>>(out);
}

// round 2
// speedup vs baseline: 1.9453x; 1.9453x over previous
#include <cuda_runtime.h>
#include <cstdint>

#define NN 100000
#define MAXE 3300000
#define SCAN_BS 512

// ---------------- scratch (static device globals) ---------------------------
__device__ __align__(256) int   g_indeg[NN];
__device__ __align__(256) int   g_outdeg[NN];
__device__ __align__(256) int   g_fill[NN];
__device__ __align__(256) int   g_rowptr[NN + 1];
__device__ __align__(256) int   g_blocksums[256];
__device__ __align__(256) int   g_esrc[MAXE];
__device__ __align__(256) float g_snorm[NN];
__device__ __align__(256) float g_dnorm[NN];
__device__ __align__(256) float g_agg[(size_t)NN * 256];  // 102.4 MB
__device__ __align__(256) float g_h[(size_t)NN * 256];    // 102.4 MB
__device__ __align__(256) float g_xm[(size_t)NN * 64];    // 25.6 MB

// ---------------- packed f32x2 helpers --------------------------------------
__device__ __forceinline__ unsigned long long pack2(float lo, float hi) {
    unsigned long long r;
    asm("mov.b64 %0, {%1, %2};" : "=l"(r) : "f"(lo), "f"(hi));
    return r;
}
__device__ __forceinline__ void fma2(unsigned long long& d, unsigned long long a,
                                     unsigned long long b) {
    asm("fma.rn.f32x2 %0, %1, %2, %3;" : "=l"(d) : "l"(a), "l"(b), "l"(d));
}
__device__ __forceinline__ float2 unpack2(unsigned long long v) {
    float2 f;
    asm("mov.b64 {%0, %1}, %2;" : "=f"(f.x), "=f"(f.y) : "l"(v));
    return f;
}

// ---------------- degrees / norms -------------------------------------------
__global__ void zero_init_kernel() {
    int i = blockIdx.x * blockDim.x + threadIdx.x;
    if (i < NN) { g_indeg[i] = 0; g_outdeg[i] = 0; g_fill[i] = 0; }
}

__global__ void degree_kernel(const int* __restrict__ src,
                              const int* __restrict__ dst, int nE) {
    int i = blockIdx.x * blockDim.x + threadIdx.x;
    if (i < nE) {
        atomicAdd(&g_outdeg[src[i]], 1);
        atomicAdd(&g_indeg[dst[i]], 1);
    }
}

__global__ void norm_kernel() {
    int i = blockIdx.x * blockDim.x + threadIdx.x;
    if (i < NN) {
        g_snorm[i] = rsqrtf(fmaxf((float)g_outdeg[i], 1.f));
        g_dnorm[i] = rsqrtf(fmaxf((float)g_indeg[i], 1.f));
    }
}

// ---------------- CSR build: scan + bucket fill ------------------------------
__global__ void scan1_kernel() {
    __shared__ int sh[SCAN_BS];
    int i = blockIdx.x * SCAN_BS + threadIdx.x;
    int v = (i < NN) ? g_indeg[i] : 0;
    sh[threadIdx.x] = v;
    __syncthreads();
    for (int off = 1; off < SCAN_BS; off <<= 1) {
        int t = (threadIdx.x >= off) ? sh[threadIdx.x - off] : 0;
        __syncthreads();
        sh[threadIdx.x] += t;
        __syncthreads();
    }
    if (i < NN) g_rowptr[i] = sh[threadIdx.x] - v;  // exclusive
    if (threadIdx.x == SCAN_BS - 1) g_blocksums[blockIdx.x] = sh[threadIdx.x];
}

__global__ void scan2_kernel(int nb) {
    __shared__ int sh[256];
    int t = threadIdx.x;
    int v = (t < nb) ? g_blocksums[t] : 0;
    sh[t] = v;
    __syncthreads();
    for (int off = 1; off < 256; off <<= 1) {
        int u = (t >= off) ? sh[t - off] : 0;
        __syncthreads();
        sh[t] += u;
        __syncthreads();
    }
    if (t < nb) g_blocksums[t] = sh[t] - v;  // exclusive block offsets
}

__global__ void scan3_kernel(int nE) {
    int i = blockIdx.x * SCAN_BS + threadIdx.x;
    if (i < NN) g_rowptr[i] += g_blocksums[blockIdx.x];
    if (i == 0) g_rowptr[NN] = nE;
}

__global__ void fillcsr_kernel(const int* __restrict__ src,
                               const int* __restrict__ dst, int nE) {
    int i = blockIdx.x * blockDim.x + threadIdx.x;
    if (i < nE) {
        int d = dst[i];
        int pos = g_rowptr[d] + atomicAdd(&g_fill[d], 1);
        g_esrc[pos] = src[i];
    }
}

// ---------------- gather aggregation (no atomics) ----------------------------
// one warp per dst node, F=256; out[v] = sum_e snorm[src_e] * x[src_e]
__global__ __launch_bounds__(256) void gather256_kernel(
    const float* __restrict__ x, float* __restrict__ out) {
    int v = (blockIdx.x * blockDim.x + threadIdx.x) >> 5;
    int lane = threadIdx.x & 31;
    if (v >= NN) return;
    int row = g_rowptr[v];
    int end = g_rowptr[v + 1];
    float4 acc0 = make_float4(0.f, 0.f, 0.f, 0.f);
    float4 acc1 = make_float4(0.f, 0.f, 0.f, 0.f);
    for (int base = row; base < end; base += 32) {
        int n = min(32, end - base);
        int s = 0;
        float w = 0.f;
        if (lane < n) { s = __ldg(&g_esrc[base + lane]); w = __ldg(&g_snorm[s]); }
        for (int k = 0; k < n; k++) {
            int sk = __shfl_sync(0xffffffffu, s, k);
            float wk = __shfl_sync(0xffffffffu, w, k);
            const float4* xr = (const float4*)(x + (size_t)sk * 256);
            float4 a = __ldg(&xr[lane]);
            float4 b = __ldg(&xr[lane + 32]);
            acc0.x += wk * a.x; acc0.y += wk * a.y;
            acc0.z += wk * a.z; acc0.w += wk * a.w;
            acc1.x += wk * b.x; acc1.y += wk * b.y;
            acc1.z += wk * b.z; acc1.w += wk * b.w;
        }
    }
    float4* op = (float4*)(out + (size_t)v * 256);
    op[lane] = acc0;
    op[lane + 32] = acc1;
}

// one warp per dst node, F=64; out[v] = dnorm[v] * sum_e x[src_e] (snorm in GEMM)
__global__ __launch_bounds__(256) void gather64_kernel(
    const float* __restrict__ x, float* __restrict__ out) {
    int v = (blockIdx.x * blockDim.x + threadIdx.x) >> 5;
    int lane = threadIdx.x & 31;
    if (v >= NN) return;
    int row = g_rowptr[v];
    int end = g_rowptr[v + 1];
    float2 acc = make_float2(0.f, 0.f);
    for (int base = row; base < end; base += 32) {
        int n = min(32, end - base);
        int s = 0;
        if (lane < n) s = __ldg(&g_esrc[base + lane]);
        for (int k = 0; k < n; k++) {
            int sk = __shfl_sync(0xffffffffu, s, k);
            float2 a = __ldg((const float2*)(x + (size_t)sk * 64) + lane);
            acc.x += a.x;
            acc.y += a.y;
        }
    }
    float w = g_dnorm[v];
    ((float2*)(out + (size_t)v * 64))[lane] = make_float2(acc.x * w, acc.y * w);
}

// ---------------- SGEMM: C = act( (A * norm[:,None]) @ W ), f32x2 FMA --------
template <int BN, int TN, bool RELU>
__global__ __launch_bounds__(256, 2) void gemm_kernel(
    const float* __restrict__ A, const float* __restrict__ W,
    const float* __restrict__ norm, float* __restrict__ C, int M, int N) {
    constexpr int BM = 128, BK = 8, TM = 8;
    constexpr int TN2 = TN / 2;
    __shared__ float As[BK][BM];
    __shared__ float Ws[BK][BN];

    const int t = threadIdx.x;
    const int tr = t >> 4;   // 0..15
    const int tc = t & 15;   // 0..15
    const int row0 = blockIdx.x * BM;
    const int col0 = blockIdx.y * BN;

    const int a_row = t >> 1;
    const int a_k4 = (t & 1) << 2;
    const bool a_ok = (row0 + a_row) < M;
    const float nrm = a_ok ? __ldg(&norm[row0 + a_row]) : 0.f;
    const float* Aptr = A + (size_t)(row0 + a_row) * 256 + a_k4;

    unsigned long long acc2[TM][TN2];
#pragma unroll
    for (int i = 0; i < TM; i++)
#pragma unroll
        for (int j = 0; j < TN2; j++) acc2[i][j] = 0ull;

    for (int k0 = 0; k0 < 256; k0 += BK) {
        float4 av = make_float4(0.f, 0.f, 0.f, 0.f);
        if (a_ok) av = *(const float4*)(Aptr + k0);
        As[a_k4 + 0][a_row] = av.x * nrm;
        As[a_k4 + 1][a_row] = av.y * nrm;
        As[a_k4 + 2][a_row] = av.z * nrm;
        As[a_k4 + 3][a_row] = av.w * nrm;

        if (BN == 128) {
            int wk = t >> 5;
            int wc = (t & 31) << 2;
            float4 wv = *(const float4*)&W[(size_t)(k0 + wk) * N + col0 + wc];
            *(float4*)&Ws[wk][wc] = wv;
        } else {  // BN == 64
            if (t < (BK * BN / 4)) {
                int wk = t / (BN / 4);
                int wc = (t % (BN / 4)) * 4;
                float4 wv = *(const float4*)&W[(size_t)(k0 + wk) * N + col0 + wc];
                *(float4*)&Ws[wk][wc] = wv;
            }
        }
        __syncthreads();

#pragma unroll
        for (int k = 0; k < BK; k++) {
            float a[TM];
            *(float4*)&a[0] = *(float4*)&As[k][tr * TM];
            *(float4*)&a[4] = *(float4*)&As[k][tr * TM + 4];
            unsigned long long b2[TN2];
#pragma unroll
            for (int jp = 0; jp < TN2; jp++)
                b2[jp] = *(const unsigned long long*)&Ws[k][tc * TN + jp * 2];
#pragma unroll
            for (int i = 0; i < TM; i++) {
                unsigned long long a2 = pack2(a[i], a[i]);
#pragma unroll
                for (int jp = 0; jp < TN2; jp++) fma2(acc2[i][jp], a2, b2[jp]);
            }
        }
        __syncthreads();
    }

#pragma unroll
    for (int i = 0; i < TM; i++) {
        int r = row0 + tr * TM + i;
        if (r < M) {
            float* crow = C + (size_t)r * N + col0 + tc * TN;
#pragma unroll
            for (int jp = 0; jp < TN2; jp += 2) {
                float2 lo = unpack2(acc2[i][jp]);
                float2 hi = unpack2(acc2[i][jp + 1]);
                float4 v = make_float4(lo.x, lo.y, hi.x, hi.y);
                if (RELU) {
                    v.x = fmaxf(v.x, 0.f); v.y = fmaxf(v.y, 0.f);
                    v.z = fmaxf(v.z, 0.f); v.w = fmaxf(v.w, 0.f);
                }
                *(float4*)(crow + jp * 2) = v;
            }
        }
    }
}

// ---------------- launch -----------------------------------------------------
extern "C" void kernel_launch(void* const* d_in, const int* in_sizes, int n_in,
                              void* d_out, int out_size) {
    const float* feat = (const float*)d_in[0];
    const int* src = (const int*)d_in[1];
    const int* dst = (const int*)d_in[2];
    const float* W0 = (const float*)d_in[3];
    const float* W1 = (const float*)d_in[4];
    const float* W2 = (const float*)d_in[5];
    float* out = (float*)d_out;
    const int nE = in_sizes[1];

    float *agg, *h, *xm, *snorm, *dnorm;
    cudaGetSymbolAddress((void**)&agg, g_agg);
    cudaGetSymbolAddress((void**)&h, g_h);
    cudaGetSymbolAddress((void**)&xm, g_xm);
    cudaGetSymbolAddress((void**)&snorm, g_snorm);
    cudaGetSymbolAddress((void**)&dnorm, g_dnorm);

    const int T = 256;
    const int NB = (NN + SCAN_BS - 1) / SCAN_BS;  // 196
    const int gemm_rows = (NN + 127) / 128;       // 782
    const int gather_blocks = (NN * 32 + T - 1) / T;  // 12500

    // degrees + norms + CSR build
    zero_init_kernel<<<(NN + T - 1) / T, T>>>();
    degree_kernel<<<(nE + T - 1) / T, T>>>(src, dst, nE);
    norm_kernel<<<(NN + T - 1) / T, T>>>();
    scan1_kernel<<<NB, SCAN_BS>>>();
    scan2_kernel<<<1, 256>>>(NB);
    scan3_kernel<<<NB, SCAN_BS>>>(nE);
    fillcsr_kernel<<<(nE + T - 1) / T, T>>>(src, dst, nE);

    // layer 0: agg = A^T (feat * snorm); h = relu((agg * dnorm) @ W0)
    gather256_kernel<<<gather_blocks, T>>>(feat, agg);
    gemm_kernel<128, 8, true><<<dim3(gemm_rows, 2), T>>>(agg, W0, dnorm, h, NN, 256);

    // layer 1
    gather256_kernel<<<gather_blocks, T>>>(h, agg);
    gemm_kernel<128, 8, true><<<dim3(gemm_rows, 2), T>>>(agg, W1, dnorm, h, NN, 256);

    // layer 2: xm = (h * snorm) @ W2; out = dnorm * (A^T xm)
    gemm_kernel<64, 4, false><<<dim3(gemm_rows, 1), T>>>(h, W2, snorm, xm, NN, 64);
    gather64_kernel<<<gather_blocks, T>>>(xm, out);
}

// round 3
// speedup vs baseline: 2.1163x; 1.0880x over previous
#include <cuda_runtime.h>
#include <mma.h>
#include <cstdint>

using namespace nvcuda;

#define NN 100000
#define NN_PAD 100096   // 782 * 128, so GEMM tiles never go OOB
#define MAXE 3300000
#define SCAN_BS 512

// ---------------- scratch (static device globals) ---------------------------
__device__ __align__(256) int   g_indeg[NN];
__device__ __align__(256) int   g_outdeg[NN];
__device__ __align__(256) int   g_fill[NN];
__device__ __align__(256) int   g_rowptr[NN + 1];
__device__ __align__(256) int   g_blocksums[256];
__device__ __align__(256) int   g_esrc[MAXE];
__device__ __align__(256) float g_snorm[NN];
__device__ __align__(256) float g_dnorm[NN];
__device__ __align__(256) float g_agg[(size_t)NN_PAD * 256];  // 102.5 MB
__device__ __align__(256) float g_h[(size_t)NN_PAD * 256];    // 102.5 MB
__device__ __align__(256) float g_xm[(size_t)NN_PAD * 64];    // 25.6 MB

// ---------------- degrees / norms -------------------------------------------
__global__ void zero_init_kernel() {
    int i = blockIdx.x * blockDim.x + threadIdx.x;
    if (i < NN) { g_indeg[i] = 0; g_outdeg[i] = 0; g_fill[i] = 0; }
}

__global__ void degree_kernel(const int* __restrict__ src,
                              const int* __restrict__ dst, int nE) {
    int i = blockIdx.x * blockDim.x + threadIdx.x;
    if (i < nE) {
        atomicAdd(&g_outdeg[src[i]], 1);
        atomicAdd(&g_indeg[dst[i]], 1);
    }
}

__global__ void norm_kernel() {
    int i = blockIdx.x * blockDim.x + threadIdx.x;
    if (i < NN) {
        g_snorm[i] = rsqrtf(fmaxf((float)g_outdeg[i], 1.f));
        g_dnorm[i] = rsqrtf(fmaxf((float)g_indeg[i], 1.f));
    }
}

// ---------------- CSR build: scan + bucket fill ------------------------------
__global__ void scan1_kernel() {
    __shared__ int sh[SCAN_BS];
    int i = blockIdx.x * SCAN_BS + threadIdx.x;
    int v = (i < NN) ? g_indeg[i] : 0;
    sh[threadIdx.x] = v;
    __syncthreads();
    for (int off = 1; off < SCAN_BS; off <<= 1) {
        int t = (threadIdx.x >= off) ? sh[threadIdx.x - off] : 0;
        __syncthreads();
        sh[threadIdx.x] += t;
        __syncthreads();
    }
    if (i < NN) g_rowptr[i] = sh[threadIdx.x] - v;  // exclusive
    if (threadIdx.x == SCAN_BS - 1) g_blocksums[blockIdx.x] = sh[threadIdx.x];
}

__global__ void scan2_kernel(int nb) {
    __shared__ int sh[256];
    int t = threadIdx.x;
    int v = (t < nb) ? g_blocksums[t] : 0;
    sh[t] = v;
    __syncthreads();
    for (int off = 1; off < 256; off <<= 1) {
        int u = (t >= off) ? sh[t - off] : 0;
        __syncthreads();
        sh[t] += u;
        __syncthreads();
    }
    if (t < nb) g_blocksums[t] = sh[t] - v;  // exclusive block offsets
}

__global__ void scan3_kernel(int nE) {
    int i = blockIdx.x * SCAN_BS + threadIdx.x;
    if (i < NN) g_rowptr[i] += g_blocksums[blockIdx.x];
    if (i == 0) g_rowptr[NN] = nE;
}

__global__ void fillcsr_kernel(const int* __restrict__ src,
                               const int* __restrict__ dst, int nE) {
    int i = blockIdx.x * blockDim.x + threadIdx.x;
    if (i < nE) {
        int d = dst[i];
        int pos = g_rowptr[d] + atomicAdd(&g_fill[d], 1);
        g_esrc[pos] = src[i];
    }
}

// ---------------- gather aggregation (no atomics) ----------------------------
// one warp per dst node, F=256; out[v] = sum_e snorm[src_e] * x[src_e]
__global__ __launch_bounds__(256) void gather256_kernel(
    const float* __restrict__ x, float* __restrict__ out) {
    int v = (blockIdx.x * blockDim.x + threadIdx.x) >> 5;
    int lane = threadIdx.x & 31;
    if (v >= NN) return;
    int row = g_rowptr[v];
    int end = g_rowptr[v + 1];
    float4 acc0 = make_float4(0.f, 0.f, 0.f, 0.f);
    float4 acc1 = make_float4(0.f, 0.f, 0.f, 0.f);
    for (int base = row; base < end; base += 32) {
        int n = min(32, end - base);
        int s = 0;
        float w = 0.f;
        if (lane < n) { s = __ldg(&g_esrc[base + lane]); w = __ldg(&g_snorm[s]); }
        for (int k = 0; k < n; k++) {
            int sk = __shfl_sync(0xffffffffu, s, k);
            float wk = __shfl_sync(0xffffffffu, w, k);
            const float4* xr = (const float4*)(x + (size_t)sk * 256);
            float4 a = __ldg(&xr[lane]);
            float4 b = __ldg(&xr[lane + 32]);
            acc0.x += wk * a.x; acc0.y += wk * a.y;
            acc0.z += wk * a.z; acc0.w += wk * a.w;
            acc1.x += wk * b.x; acc1.y += wk * b.y;
            acc1.z += wk * b.z; acc1.w += wk * b.w;
        }
    }
    float4* op = (float4*)(out + (size_t)v * 256);
    op[lane] = acc0;
    op[lane + 32] = acc1;
}

// one warp per dst node, F=64; out[v] = dnorm[v] * sum_e x[src_e] (snorm in GEMM)
__global__ __launch_bounds__(256) void gather64_kernel(
    const float* __restrict__ x, float* __restrict__ out) {
    int v = (blockIdx.x * blockDim.x + threadIdx.x) >> 5;
    int lane = threadIdx.x & 31;
    if (v >= NN) return;
    int row = g_rowptr[v];
    int end = g_rowptr[v + 1];
    float2 acc = make_float2(0.f, 0.f);
    for (int base = row; base < end; base += 32) {
        int n = min(32, end - base);
        int s = 0;
        if (lane < n) s = __ldg(&g_esrc[base + lane]);
        for (int k = 0; k < n; k++) {
            int sk = __shfl_sync(0xffffffffu, s, k);
            float2 a = __ldg((const float2*)(x + (size_t)sk * 64) + lane);
            acc.x += a.x;
            acc.y += a.y;
        }
    }
    float w = g_dnorm[v];
    ((float2*)(out + (size_t)v * 64))[lane] = make_float2(acc.x * w, acc.y * w);
}

// ---------------- TF32 tensor-core GEMM --------------------------------------
// C = act( (A * norm[:,None]) @ W ),  K = 256 fixed.
// BM=128, BN=64, BK=32; 8 warps, each computes a 32x32 warp tile (2x2 WMMA).
// A rows are padded to NN_PAD so full-tile loads/stores are always in-bounds;
// norm is guarded (0 beyond M) so pad rows contribute garbage only to pad rows.
template <bool RELU>
__global__ __launch_bounds__(256, 2) void gemm_tf32_kernel(
    const float* __restrict__ A, const float* __restrict__ W,
    const float* __restrict__ norm, float* __restrict__ C, int M, int N) {
    constexpr int BM = 128, BN = 64, BK = 32;
    constexpr int APAD = 8, BPAD = 8;
    __shared__ float As[BM][BK + APAD];   // 128*40*4 = 20.5 KB
    __shared__ float Bs[BK][BN + BPAD];   // 32*72*4  = 9.2 KB

    const int t = threadIdx.x;
    const int warp = t >> 5;
    const int wm = warp >> 1;   // 0..3 -> 32-row strip
    const int wn = warp & 1;    // 0..1 -> 32-col strip
    const int row0 = blockIdx.x * BM;
    const int col0 = blockIdx.y * BN;

    // A-load mapping: 128 rows x 32 cols = 1024 float4; thread t -> row t>>1,
    // half (t&1): 4 float4 at cols (t&1)*16 + {0,4,8,12}
    const int a_row = t >> 1;
    const int a_c0 = (t & 1) * 16;
    const bool a_ok = (row0 + a_row) < M;
    const float nrm = a_ok ? __ldg(&norm[row0 + a_row]) : 0.f;
    const float* Aptr = A + (size_t)(row0 + a_row) * 256 + a_c0;

    // B-load mapping: 32 rows x 64 cols = 512 float4; thread t -> row t>>3,
    // 2 float4 at cols (t&7)*8 + {0,4}
    const int b_row = t >> 3;
    const int b_c0 = (t & 7) * 8;

    wmma::fragment<wmma::accumulator, 16, 16, 8, float> acc[2][2];
#pragma unroll
    for (int i = 0; i < 2; i++)
#pragma unroll
        for (int j = 0; j < 2; j++) wmma::fill_fragment(acc[i][j], 0.f);

    for (int k0 = 0; k0 < 256; k0 += BK) {
#pragma unroll
        for (int q = 0; q < 4; q++) {
            float4 av = *(const float4*)(Aptr + k0 + q * 4);
            if (!a_ok) av = make_float4(0.f, 0.f, 0.f, 0.f);
            As[a_row][a_c0 + q * 4 + 0] = av.x * nrm;
            As[a_row][a_c0 + q * 4 + 1] = av.y * nrm;
            As[a_row][a_c0 + q * 4 + 2] = av.z * nrm;
            As[a_row][a_c0 + q * 4 + 3] = av.w * nrm;
        }
#pragma unroll
        for (int q = 0; q < 2; q++) {
            float4 wv = *(const float4*)&W[(size_t)(k0 + b_row) * N + col0 + b_c0 + q * 4];
            *(float4*)&Bs[b_row][b_c0 + q * 4] = wv;
        }
        __syncthreads();

#pragma unroll
        for (int kk = 0; kk < BK; kk += 8) {
            wmma::fragment<wmma::matrix_a, 16, 16, 8, wmma::precision::tf32,
                           wmma::row_major> af[2];
            wmma::fragment<wmma::matrix_b, 16, 16, 8, wmma::precision::tf32,
                           wmma::row_major> bf[2];
#pragma unroll
            for (int i = 0; i < 2; i++) {
                wmma::load_matrix_sync(af[i], &As[wm * 32 + i * 16][kk], BK + APAD);
#pragma unroll
                for (int e = 0; e < af[i].num_elements; e++)
                    af[i].x[e] = wmma::__float_to_tf32(af[i].x[e]);
            }
#pragma unroll
            for (int j = 0; j < 2; j++) {
                wmma::load_matrix_sync(bf[j], &Bs[kk][wn * 32 + j * 16], BN + BPAD);
#pragma unroll
                for (int e = 0; e < bf[j].num_elements; e++)
                    bf[j].x[e] = wmma::__float_to_tf32(bf[j].x[e]);
            }
#pragma unroll
            for (int i = 0; i < 2; i++)
#pragma unroll
                for (int j = 0; j < 2; j++)
                    wmma::mma_sync(acc[i][j], af[i], bf[j], acc[i][j]);
        }
        __syncthreads();
    }

#pragma unroll
    for (int i = 0; i < 2; i++)
#pragma unroll
        for (int j = 0; j < 2; j++) {
            if (RELU) {
#pragma unroll
                for (int e = 0; e < acc[i][j].num_elements; e++)
                    acc[i][j].x[e] = fmaxf(acc[i][j].x[e], 0.f);
            }
            float* cptr = C + (size_t)(row0 + wm * 32 + i * 16) * N +
                          col0 + wn * 32 + j * 16;
            wmma::store_matrix_sync(cptr, acc[i][j], N, wmma::mem_row_major);
        }
}

// ---------------- launch -----------------------------------------------------
extern "C" void kernel_launch(void* const* d_in, const int* in_sizes, int n_in,
                              void* d_out, int out_size) {
    const float* feat = (const float*)d_in[0];
    const int* src = (const int*)d_in[1];
    const int* dst = (const int*)d_in[2];
    const float* W0 = (const float*)d_in[3];
    const float* W1 = (const float*)d_in[4];
    const float* W2 = (const float*)d_in[5];
    float* out = (float*)d_out;
    const int nE = in_sizes[1];

    float *agg, *h, *xm, *snorm, *dnorm;
    cudaGetSymbolAddress((void**)&agg, g_agg);
    cudaGetSymbolAddress((void**)&h, g_h);
    cudaGetSymbolAddress((void**)&xm, g_xm);
    cudaGetSymbolAddress((void**)&snorm, g_snorm);
    cudaGetSymbolAddress((void**)&dnorm, g_dnorm);

    const int T = 256;
    const int NB = (NN + SCAN_BS - 1) / SCAN_BS;      // 196
    const int gemm_rows = NN_PAD / 128;               // 782
    const int gather_blocks = (NN * 32 + T - 1) / T;  // 12500

    // degrees + norms + CSR build
    zero_init_kernel<<<(NN + T - 1) / T, T>>>();
    degree_kernel<<<(nE + T - 1) / T, T>>>(src, dst, nE);
    norm_kernel<<<(NN + T - 1) / T, T>>>();
    scan1_kernel<<<NB, SCAN_BS>>>();
    scan2_kernel<<<1, 256>>>(NB);
    scan3_kernel<<<NB, SCAN_BS>>>(nE);
    fillcsr_kernel<<<(nE + T - 1) / T, T>>>(src, dst, nE);

    // layer 0: agg = A^T (feat * snorm); h = relu((agg * dnorm) @ W0)
    gather256_kernel<<<gather_blocks, T>>>(feat, agg);
    gemm_tf32_kernel<true><<<dim3(gemm_rows, 4), T>>>(agg, W0, dnorm, h, NN, 256);

    // layer 1
    gather256_kernel<<<gather_blocks, T>>>(h, agg);
    gemm_tf32_kernel<true><<<dim3(gemm_rows, 4), T>>>(agg, W1, dnorm, h, NN, 256);

    // layer 2: xm = (h * snorm) @ W2; out = dnorm * (A^T xm)
    gemm_tf32_kernel<false><<<dim3(gemm_rows, 1), T>>>(h, W2, snorm, xm, NN, 64);
    gather64_kernel<<<gather_blocks, T>>>(xm, out);
}

// round 4
// speedup vs baseline: 2.2898x; 1.0820x over previous
#include <cuda_runtime.h>
#include <mma.h>
#include <cstdint>

using namespace nvcuda;

#define NN 100000
#define NN_PAD 100096   // 782 * 128, so GEMM tiles never go OOB
#define MAXE 3300000
#define SCAN_BS 512

// ---------------- scratch (static device globals) ---------------------------
__device__ __align__(256) int   g_indeg[NN];
__device__ __align__(256) int   g_outdeg[NN];
__device__ __align__(256) int   g_fill[NN];
__device__ __align__(256) int   g_rowptr[NN + 1];
__device__ __align__(256) int   g_blocksums[256];
__device__ __align__(256) int   g_esrc[MAXE];
__device__ __align__(256) float g_snorm[NN];
__device__ __align__(256) float g_dnorm[NN];
__device__ __align__(256) float g_agg[(size_t)NN_PAD * 256];  // 102.5 MB
__device__ __align__(256) float g_h[(size_t)NN_PAD * 256];    // 102.5 MB
__device__ __align__(256) float g_xm[(size_t)NN_PAD * 64];    // 25.6 MB

// ---------------- degrees / norms -------------------------------------------
__global__ void zero_init_kernel() {
    int i = blockIdx.x * blockDim.x + threadIdx.x;
    if (i < NN) { g_indeg[i] = 0; g_outdeg[i] = 0; g_fill[i] = 0; }
}

__global__ void degree_kernel(const int* __restrict__ src,
                              const int* __restrict__ dst, int nE) {
    int i = blockIdx.x * blockDim.x + threadIdx.x;
    if (i < nE) {
        atomicAdd(&g_outdeg[src[i]], 1);
        atomicAdd(&g_indeg[dst[i]], 1);
    }
}

__global__ void norm_kernel() {
    int i = blockIdx.x * blockDim.x + threadIdx.x;
    if (i < NN) {
        g_snorm[i] = rsqrtf(fmaxf((float)g_outdeg[i], 1.f));
        g_dnorm[i] = rsqrtf(fmaxf((float)g_indeg[i], 1.f));
    }
}

// ---------------- CSR build: scan + bucket fill ------------------------------
__global__ void scan1_kernel() {
    __shared__ int sh[SCAN_BS];
    int i = blockIdx.x * SCAN_BS + threadIdx.x;
    int v = (i < NN) ? g_indeg[i] : 0;
    sh[threadIdx.x] = v;
    __syncthreads();
    for (int off = 1; off < SCAN_BS; off <<= 1) {
        int t = (threadIdx.x >= off) ? sh[threadIdx.x - off] : 0;
        __syncthreads();
        sh[threadIdx.x] += t;
        __syncthreads();
    }
    if (i < NN) g_rowptr[i] = sh[threadIdx.x] - v;  // exclusive
    if (threadIdx.x == SCAN_BS - 1) g_blocksums[blockIdx.x] = sh[threadIdx.x];
}

__global__ void scan2_kernel(int nb) {
    __shared__ int sh[256];
    int t = threadIdx.x;
    int v = (t < nb) ? g_blocksums[t] : 0;
    sh[t] = v;
    __syncthreads();
    for (int off = 1; off < 256; off <<= 1) {
        int u = (t >= off) ? sh[t - off] : 0;
        __syncthreads();
        sh[t] += u;
        __syncthreads();
    }
    if (t < nb) g_blocksums[t] = sh[t] - v;  // exclusive block offsets
}

__global__ void scan3_kernel(int nE) {
    int i = blockIdx.x * SCAN_BS + threadIdx.x;
    if (i < NN) g_rowptr[i] += g_blocksums[blockIdx.x];
    if (i == 0) g_rowptr[NN] = nE;
}

__global__ void fillcsr_kernel(const int* __restrict__ src,
                               const int* __restrict__ dst, int nE) {
    int i = blockIdx.x * blockDim.x + threadIdx.x;
    if (i < nE) {
        int d = dst[i];
        int pos = g_rowptr[d] + atomicAdd(&g_fill[d], 1);
        g_esrc[pos] = src[i];
    }
}

// ---------------- gather aggregation (no atomics) ----------------------------
// one warp per dst node, F=256; out[v] = sum_e snorm[src_e] * x[src_e]
// dual-edge unroll: 4 independent LDG.128 in flight per iteration
__global__ __launch_bounds__(256) void gather256_kernel(
    const float* __restrict__ x, float* __restrict__ out) {
    int v = (blockIdx.x * blockDim.x + threadIdx.x) >> 5;
    int lane = threadIdx.x & 31;
    if (v >= NN) return;
    int row = g_rowptr[v];
    int end = g_rowptr[v + 1];
    float4 acc0 = make_float4(0.f, 0.f, 0.f, 0.f);
    float4 acc1 = make_float4(0.f, 0.f, 0.f, 0.f);
    for (int base = row; base < end; base += 32) {
        int n = min(32, end - base);
        int s = 0;
        float w = 0.f;
        if (lane < n) { s = __ldg(&g_esrc[base + lane]); w = __ldg(&g_snorm[s]); }
        int k = 0;
        for (; k + 2 <= n; k += 2) {
            int s0 = __shfl_sync(0xffffffffu, s, k);
            int s1 = __shfl_sync(0xffffffffu, s, k + 1);
            float w0 = __shfl_sync(0xffffffffu, w, k);
            float w1 = __shfl_sync(0xffffffffu, w, k + 1);
            const float4* r0 = (const float4*)(x + (size_t)s0 * 256);
            const float4* r1 = (const float4*)(x + (size_t)s1 * 256);
            float4 a0 = __ldg(&r0[lane]);
            float4 b0 = __ldg(&r0[lane + 32]);
            float4 a1 = __ldg(&r1[lane]);
            float4 b1 = __ldg(&r1[lane + 32]);
            acc0.x = fmaf(w0, a0.x, fmaf(w1, a1.x, acc0.x));
            acc0.y = fmaf(w0, a0.y, fmaf(w1, a1.y, acc0.y));
            acc0.z = fmaf(w0, a0.z, fmaf(w1, a1.z, acc0.z));
            acc0.w = fmaf(w0, a0.w, fmaf(w1, a1.w, acc0.w));
            acc1.x = fmaf(w0, b0.x, fmaf(w1, b1.x, acc1.x));
            acc1.y = fmaf(w0, b0.y, fmaf(w1, b1.y, acc1.y));
            acc1.z = fmaf(w0, b0.z, fmaf(w1, b1.z, acc1.z));
            acc1.w = fmaf(w0, b0.w, fmaf(w1, b1.w, acc1.w));
        }
        if (k < n) {
            int s0 = __shfl_sync(0xffffffffu, s, k);
            float w0 = __shfl_sync(0xffffffffu, w, k);
            const float4* r0 = (const float4*)(x + (size_t)s0 * 256);
            float4 a0 = __ldg(&r0[lane]);
            float4 b0 = __ldg(&r0[lane + 32]);
            acc0.x = fmaf(w0, a0.x, acc0.x);
            acc0.y = fmaf(w0, a0.y, acc0.y);
            acc0.z = fmaf(w0, a0.z, acc0.z);
            acc0.w = fmaf(w0, a0.w, acc0.w);
            acc1.x = fmaf(w0, b0.x, acc1.x);
            acc1.y = fmaf(w0, b0.y, acc1.y);
            acc1.z = fmaf(w0, b0.z, acc1.z);
            acc1.w = fmaf(w0, b0.w, acc1.w);
        }
    }
    float4* op = (float4*)(out + (size_t)v * 256);
    op[lane] = acc0;
    op[lane + 32] = acc1;
}

// one warp per dst node, F=64; out[v] = dnorm[v] * sum_e x[src_e] (snorm in GEMM)
__global__ __launch_bounds__(256) void gather64_kernel(
    const float* __restrict__ x, float* __restrict__ out) {
    int v = (blockIdx.x * blockDim.x + threadIdx.x) >> 5;
    int lane = threadIdx.x & 31;
    if (v >= NN) return;
    int row = g_rowptr[v];
    int end = g_rowptr[v + 1];
    float2 acc = make_float2(0.f, 0.f);
    for (int base = row; base < end; base += 32) {
        int n = min(32, end - base);
        int s = 0;
        if (lane < n) s = __ldg(&g_esrc[base + lane]);
        int k = 0;
        for (; k + 4 <= n; k += 4) {
            int s0 = __shfl_sync(0xffffffffu, s, k);
            int s1 = __shfl_sync(0xffffffffu, s, k + 1);
            int s2 = __shfl_sync(0xffffffffu, s, k + 2);
            int s3 = __shfl_sync(0xffffffffu, s, k + 3);
            float2 a0 = __ldg((const float2*)(x + (size_t)s0 * 64) + lane);
            float2 a1 = __ldg((const float2*)(x + (size_t)s1 * 64) + lane);
            float2 a2 = __ldg((const float2*)(x + (size_t)s2 * 64) + lane);
            float2 a3 = __ldg((const float2*)(x + (size_t)s3 * 64) + lane);
            acc.x += (a0.x + a1.x) + (a2.x + a3.x);
            acc.y += (a0.y + a1.y) + (a2.y + a3.y);
        }
        for (; k < n; k++) {
            int s0 = __shfl_sync(0xffffffffu, s, k);
            float2 a0 = __ldg((const float2*)(x + (size_t)s0 * 64) + lane);
            acc.x += a0.x;
            acc.y += a0.y;
        }
    }
    float w = g_dnorm[v];
    ((float2*)(out + (size_t)v * 64))[lane] = make_float2(acc.x * w, acc.y * w);
}

// ---------------- TF32 tensor-core GEMM --------------------------------------
// C = act( (A * norm[:,None]) @ W ),  K = 256 fixed.
// BM=128, BN=64, BK=32; 8 warps, 32x32 warp tile (2x2 WMMA m16n16k8).
// tf32 conversion happens ONCE at smem-store; global loads for tile k0+32 are
// prefetched into registers while MMAs consume tile k0 (reg double-buffer).
template <bool RELU>
__global__ __launch_bounds__(256, 2) void gemm_tf32_kernel(
    const float* __restrict__ A, const float* __restrict__ W,
    const float* __restrict__ norm, float* __restrict__ C, int M, int N) {
    constexpr int BM = 128, BN = 64, BK = 32;
    constexpr int APAD = 8, BPAD = 8;
    __shared__ float As[BM][BK + APAD];   // 20.5 KB
    __shared__ float Bs[BK][BN + BPAD];   // 9.2 KB

    const int t = threadIdx.x;
    const int warp = t >> 5;
    const int wm = warp >> 1;   // 0..3 -> 32-row strip
    const int wn = warp & 1;    // 0..1 -> 32-col strip
    const int row0 = blockIdx.x * BM;
    const int col0 = blockIdx.y * BN;

    // A-load mapping: thread t -> row t>>1, 4 float4 at cols (t&1)*16 + q*4
    const int a_row = t >> 1;
    const int a_c0 = (t & 1) * 16;
    const bool a_ok = (row0 + a_row) < M;
    const float nrm = a_ok ? __ldg(&norm[row0 + a_row]) : 0.f;
    const float* Aptr = A + (size_t)(row0 + a_row) * 256 + a_c0;

    // B-load mapping: thread t -> row t>>3, 2 float4 at cols (t&7)*8 + q*4
    const int b_row = t >> 3;
    const int b_c0 = (t & 7) * 8;
    const float* Wptr = W + (size_t)b_row * N + col0 + b_c0;

    wmma::fragment<wmma::accumulator, 16, 16, 8, float> acc[2][2];
#pragma unroll
    for (int i = 0; i < 2; i++)
#pragma unroll
        for (int j = 0; j < 2; j++) wmma::fill_fragment(acc[i][j], 0.f);

    float4 ar[4], br[2];
    // preload tile k0=0
#pragma unroll
    for (int q = 0; q < 4; q++) ar[q] = *(const float4*)(Aptr + q * 4);
#pragma unroll
    for (int q = 0; q < 2; q++) br[q] = *(const float4*)(Wptr + q * 4);

    auto store_tiles = [&]() {
#pragma unroll
        for (int q = 0; q < 4; q++) {
            As[a_row][a_c0 + q * 4 + 0] = wmma::__float_to_tf32(ar[q].x * nrm);
            As[a_row][a_c0 + q * 4 + 1] = wmma::__float_to_tf32(ar[q].y * nrm);
            As[a_row][a_c0 + q * 4 + 2] = wmma::__float_to_tf32(ar[q].z * nrm);
            As[a_row][a_c0 + q * 4 + 3] = wmma::__float_to_tf32(ar[q].w * nrm);
        }
#pragma unroll
        for (int q = 0; q < 2; q++) {
            Bs[b_row][b_c0 + q * 4 + 0] = wmma::__float_to_tf32(br[q].x);
            Bs[b_row][b_c0 + q * 4 + 1] = wmma::__float_to_tf32(br[q].y);
            Bs[b_row][b_c0 + q * 4 + 2] = wmma::__float_to_tf32(br[q].z);
            Bs[b_row][b_c0 + q * 4 + 3] = wmma::__float_to_tf32(br[q].w);
        }
    };

    store_tiles();
    __syncthreads();

    for (int k0 = 0; k0 < 256; k0 += BK) {
        const bool has_next = (k0 + BK) < 256;
        if (has_next) {  // prefetch next tile into registers
#pragma unroll
            for (int q = 0; q < 4; q++)
                ar[q] = *(const float4*)(Aptr + k0 + BK + q * 4);
#pragma unroll
            for (int q = 0; q < 2; q++)
                br[q] = *(const float4*)(Wptr + (size_t)(k0 + BK) * N -
                                         (size_t)b_row * N + (size_t)(b_row)*N + q * 4 +
                                         (size_t)0) ;
        }
        // (note: W row index is k0+BK+b_row; rewritten plainly below)
        if (has_next) {
#pragma unroll
            for (int q = 0; q < 2; q++)
                br[q] = *(const float4*)&W[(size_t)(k0 + BK + b_row) * N + col0 + b_c0 + q * 4];
        }

#pragma unroll
        for (int kk = 0; kk < BK; kk += 8) {
            wmma::fragment<wmma::matrix_a, 16, 16, 8, wmma::precision::tf32,
                           wmma::row_major> af[2];
            wmma::fragment<wmma::matrix_b, 16, 16, 8, wmma::precision::tf32,
                           wmma::row_major> bf[2];
#pragma unroll
            for (int i = 0; i < 2; i++)
                wmma::load_matrix_sync(af[i], &As[wm * 32 + i * 16][kk], BK + APAD);
#pragma unroll
            for (int j = 0; j < 2; j++)
                wmma::load_matrix_sync(bf[j], &Bs[kk][wn * 32 + j * 16], BN + BPAD);
#pragma unroll
            for (int i = 0; i < 2; i++)
#pragma unroll
                for (int j = 0; j < 2; j++)
                    wmma::mma_sync(acc[i][j], af[i], bf[j], acc[i][j]);
        }
        __syncthreads();
        if (has_next) {
            store_tiles();
            __syncthreads();
        }
    }

#pragma unroll
    for (int i = 0; i < 2; i++)
#pragma unroll
        for (int j = 0; j < 2; j++) {
            if (RELU) {
#pragma unroll
                for (int e = 0; e < acc[i][j].num_elements; e++)
                    acc[i][j].x[e] = fmaxf(acc[i][j].x[e], 0.f);
            }
            float* cptr = C + (size_t)(row0 + wm * 32 + i * 16) * N +
                          col0 + wn * 32 + j * 16;
            wmma::store_matrix_sync(cptr, acc[i][j], N, wmma::mem_row_major);
        }
}

// ---------------- launch -----------------------------------------------------
extern "C" void kernel_launch(void* const* d_in, const int* in_sizes, int n_in,
                              void* d_out, int out_size) {
    const float* feat = (const float*)d_in[0];
    const int* src = (const int*)d_in[1];
    const int* dst = (const int*)d_in[2];
    const float* W0 = (const float*)d_in[3];
    const float* W1 = (const float*)d_in[4];
    const float* W2 = (const float*)d_in[5];
    float* out = (float*)d_out;
    const int nE = in_sizes[1];

    float *agg, *h, *xm, *snorm, *dnorm;
    cudaGetSymbolAddress((void**)&agg, g_agg);
    cudaGetSymbolAddress((void**)&h, g_h);
    cudaGetSymbolAddress((void**)&xm, g_xm);
    cudaGetSymbolAddress((void**)&snorm, g_snorm);
    cudaGetSymbolAddress((void**)&dnorm, g_dnorm);

    const int T = 256;
    const int NB = (NN + SCAN_BS - 1) / SCAN_BS;      // 196
    const int gemm_rows = NN_PAD / 128;               // 782
    const int gather_blocks = (NN * 32 + T - 1) / T;  // 12500

    // degrees + norms + CSR build
    zero_init_kernel<<<(NN + T - 1) / T, T>>>();
    degree_kernel<<<(nE + T - 1) / T, T>>>(src, dst, nE);
    norm_kernel<<<(NN + T - 1) / T, T>>>();
    scan1_kernel<<<NB, SCAN_BS>>>();
    scan2_kernel<<<1, 256>>>(NB);
    scan3_kernel<<<NB, SCAN_BS>>>(nE);
    fillcsr_kernel<<<(nE + T - 1) / T, T>>>(src, dst, nE);

    // layer 0: agg = A^T (feat * snorm); h = relu((agg * dnorm) @ W0)
    gather256_kernel<<<gather_blocks, T>>>(feat, agg);
    gemm_tf32_kernel<true><<<dim3(gemm_rows, 4), T>>>(agg, W0, dnorm, h, NN, 256);

    // layer 1
    gather256_kernel<<<gather_blocks, T>>>(h, agg);
    gemm_tf32_kernel<true><<<dim3(gemm_rows, 4), T>>>(agg, W1, dnorm, h, NN, 256);

    // layer 2: xm = (h * snorm) @ W2; out = dnorm * (A^T xm)
    gemm_tf32_kernel<false><<<dim3(gemm_rows, 1), T>>>(h, W2, snorm, xm, NN, 64);
    gather64_kernel<<<gather_blocks, T>>>(xm, out);
}